// round 16
// baseline (speedup 1.0000x reference)
#include <cuda_runtime.h>

// Reverse (suffix) cumulative sum along dim=1.
// x: (2048, 32768) fp32. out[b, j] = sum_{k >= j} x[b, k].
//
// FINAL: converged HBM/LTS-bound kernel (~6.7 TB/s effective demand
// throughput == B300 LTS chip cap; 7 structural alternatives measured
// equal or slower).
//  - One CTA per row, 1024 threads. 256-bit vector ops (LDG.E.256 /
//    STG.E.256 via ld/st.global.v8.f32): thread holds 4 slots of 8
//    consecutive floats at warp_base + i*256 + lane*8 -> every memory
//    instruction covers 8 contiguous 128B lines (full-width wavefronts).
//  - 3-level suffix scan: 7 serial adds inside each float8 -> per-slot
//    warp shfl suffix scans -> register suffix over slots -> single-
//    barrier block scan of 32 warp totals (every warp redundantly scans
//    and extracts its own offset via shfl; no second barrier).
//  - Default cache policy (streaming hints, TMA store, L2 prefetch all
//    measured slower on sm_103a).

#define N_COLS   32768
#define THREADS  1024
#define SLOTS    4        // float8s per thread
#define VEC      8        // floats per vector op

__global__ __launch_bounds__(THREADS, 1)
void revcumsum_kernel(const float* __restrict__ x, float* __restrict__ out) {
    const long long base = (long long)blockIdx.x * N_COLS;
    const int t    = threadIdx.x;
    const int lane = t & 31;
    const int wid  = t >> 5;

    const float* __restrict__ xin = x + base + wid * 1024 + lane * VEC;

    // ---- 256-bit coalesced loads (front-batched for max MLP) ----
    float v[SLOTS][VEC];
    #pragma unroll
    for (int i = 0; i < SLOTS; i++) {
        asm volatile(
            "ld.global.v8.f32 {%0,%1,%2,%3,%4,%5,%6,%7}, [%8];"
            : "=f"(v[i][0]), "=f"(v[i][1]), "=f"(v[i][2]), "=f"(v[i][3]),
              "=f"(v[i][4]), "=f"(v[i][5]), "=f"(v[i][6]), "=f"(v[i][7])
            : "l"(xin + i * 256));
    }

    // ---- suffix scan inside each float8; s[i] = group sum ----
    float s[SLOTS];
    #pragma unroll
    for (int i = 0; i < SLOTS; i++) {
        #pragma unroll
        for (int j = VEC - 2; j >= 0; j--) v[i][j] += v[i][j + 1];
        s[i] = v[i][0];
    }

    // ---- per-slot warp suffix scan over lanes ----
    float excl[SLOTS];   // sum of s[i] for lanes > my lane
    float T[SLOTS];      // warp-wide total of slot i
    #pragma unroll
    for (int i = 0; i < SLOTS; i++) {
        float incl = s[i];
        #pragma unroll
        for (int d = 1; d < 32; d <<= 1) {
            float tmp = __shfl_down_sync(0xFFFFFFFFu, incl, d);
            if (lane + d < 32) incl += tmp;
        }
        excl[i] = incl - s[i];
        T[i]    = __shfl_sync(0xFFFFFFFFu, incl, 0);
    }

    // ---- register suffix over slots: O[i] = sum of T[i'] for i' > i ----
    float O[SLOTS];
    O[SLOTS - 1] = 0.0f;
    #pragma unroll
    for (int i = SLOTS - 2; i >= 0; i--) O[i] = O[i + 1] + T[i + 1];
    const float warp_total = O[0] + T[0];

    // ---- block suffix scan over 32 warp totals: single barrier ----
    __shared__ float warp_tot[32];
    if (lane == 0) warp_tot[wid] = warp_total;
    __syncthreads();

    float w  = warp_tot[lane];
    float iw = w;
    #pragma unroll
    for (int d = 1; d < 32; d <<= 1) {
        float tmp = __shfl_down_sync(0xFFFFFFFFu, iw, d);
        if (lane + d < 32) iw += tmp;
    }
    const float woff = __shfl_sync(0xFFFFFFFFu, iw - w, wid);

    // ---- apply offsets, 256-bit coalesced stores ----
    float* __restrict__ o = out + base + wid * 1024 + lane * VEC;
    #pragma unroll
    for (int i = 0; i < SLOTS; i++) {
        const float off = woff + O[i] + excl[i];
        float w0 = v[i][0] + off, w1 = v[i][1] + off;
        float w2 = v[i][2] + off, w3 = v[i][3] + off;
        float w4 = v[i][4] + off, w5 = v[i][5] + off;
        float w6 = v[i][6] + off, w7 = v[i][7] + off;
        asm volatile(
            "st.global.v8.f32 [%0], {%1,%2,%3,%4,%5,%6,%7,%8};"
            :: "l"(o + i * 256),
               "f"(w0), "f"(w1), "f"(w2), "f"(w3),
               "f"(w4), "f"(w5), "f"(w6), "f"(w7)
            : "memory");
    }
}

extern "C" void kernel_launch(void* const* d_in, const int* in_sizes, int n_in,
                              void* d_out, int out_size) {
    const float* x = (const float*)d_in[0];
    float* out = (float*)d_out;
    const int n    = in_sizes[0];       // B * N
    const int rows = n / N_COLS;        // 2048
    revcumsum_kernel<<<rows, THREADS>>>(x, out);
}